// round 10
// baseline (speedup 1.0000x reference)
#include <cuda_runtime.h>
#include <cuda_bf16.h>
#include <cstdint>

// Problem constants
#define BB 8
#define CHN 512
#define HH 80
#define WW 80
#define HW 6400
#define CR 32

// ---------------- device scratch ----------------
__device__ float g_means[2 * BB * 160 * CHN];   // [z][b][p][c]
__device__ float g_yz[2 * BB * CR * 160];       // [z][b][cr][160]
__device__ float g_s[4 * BB * CHN * 80];        // [a][b][o][80]
__device__ float g_wr[CHN * 1024];              // W fragment-order tf32
// sync: [0..7] mean[b] (tgt 1024), [8..15] yz[b] (tgt 40),
//       [16..23] s[b] (tgt 32), [24] tile ticket, [25] wrepack (tgt 128)
__device__ int g_sync[32];

// ---------------- helpers ----------------
__device__ __forceinline__ unsigned f2tf32(float x) {
    unsigned u;
    asm("cvt.rna.tf32.f32 %0, %1;" : "=r"(u) : "f"(x));
    return u;
}

__device__ __forceinline__ void mma_tf32(float d[4], const unsigned a0, const unsigned a1,
                                         const unsigned a2, const unsigned a3,
                                         const unsigned b0, const unsigned b1) {
    asm volatile(
        "mma.sync.aligned.m16n8k8.row.col.f32.tf32.tf32.f32 "
        "{%0,%1,%2,%3}, {%4,%5,%6,%7}, {%8,%9}, {%0,%1,%2,%3};\n"
        : "+f"(d[0]), "+f"(d[1]), "+f"(d[2]), "+f"(d[3])
        : "r"(a0), "r"(a1), "r"(a2), "r"(a3), "r"(b0), "r"(b1));
}

#define CP_ASYNC16(dst_u32, src_ptr) \
    asm volatile("cp.async.cg.shared.global [%0], [%1], 16;\n" :: "r"(dst_u32), "l"(src_ptr))
#define CP_COMMIT() asm volatile("cp.async.commit_group;\n" ::)
#define CP_WAIT1()  asm volatile("cp.async.wait_group 1;\n" ::)
#define CP_WAIT0()  asm volatile("cp.async.wait_group 0;\n" ::)

__device__ __forceinline__ void spin_until(const int* cnt, int target) {
    if (threadIdx.x == 0) {
        while (*((volatile int*)cnt) < target) __nanosleep(128);
    }
    __syncthreads();
}
__device__ __forceinline__ void signal(int* cnt) {
    __threadfence();
    __syncthreads();
    if (threadIdx.x == 0) atomicAdd(cnt, 1);
}

// ---------------- kernel 0: counter reset ----------------
__global__ void zero_kernel() {
    if (threadIdx.x < 32) g_sync[threadIdx.x] = 0;
}

// ---------------- persistent mega kernel ----------------
#define MEAN_CTAS 64
#define WREP_CTAS 128
#define GEMM_TILES 1600

#define BM 128
#define BN 128
#define BK 32
#define A_STAGE_FLOATS 4096
#define XS_STRIDE 136
#define X_STAGE_FLOATS (BK * XS_STRIDE)   // 4352
#define STAGE_FLOATS (A_STAGE_FLOATS + X_STAGE_FLOATS)  // 8448
#define NSTAGE 3
#define GEMM_SMEM (NSTAGE * STAGE_FLOATS * 4)           // 101376 bytes

__global__ __launch_bounds__(256, 2)
void mega_kernel(const float* __restrict__ rgb, const float* __restrict__ t,
                 const float* __restrict__ w_fuse,
                 const float* __restrict__ w_r1, const float* __restrict__ w_t1,
                 const float* __restrict__ bn_g, const float* __restrict__ bn_b,
                 const float* __restrict__ bn_m, const float* __restrict__ bn_v,
                 const float* __restrict__ w_fh1, const float* __restrict__ w_fw1,
                 const float* __restrict__ w_fh2, const float* __restrict__ w_fw2,
                 float* __restrict__ out) {
    extern __shared__ float dynsmem[];
    __shared__ int s_ticket;
    const int bid = blockIdx.x;
    const int tid = threadIdx.x;

    if (bid < MEAN_CTAS) {
        // ======== phase M: means (units u = bid + 64*j, j < 128; u -> b,z,c) ========
        float* buf0 = dynsmem;
        float* buf1 = dynsmem + HW;
        auto issue_unit = [&](int j, float* buf) {
            const int u = bid + MEAN_CTAS * j;
            const int b = u >> 10, z = (u >> 9) & 1, c = u & 511;
            const float* src = (z ? t : rgb) + ((size_t)(b * CHN) + c) * HW;
            for (int i = tid; i < HW / 4; i += 256) {
                unsigned d = (unsigned)__cvta_generic_to_shared(buf + i * 4);
                CP_ASYNC16(d, src + i * 4);
            }
        };
        issue_unit(0, buf0); CP_COMMIT();
        for (int j = 0; j < 128; ++j) {
            float* cur = (j & 1) ? buf1 : buf0;
            if (j + 1 < 128) { issue_unit(j + 1, (j & 1) ? buf0 : buf1); CP_COMMIT(); CP_WAIT1(); }
            else CP_WAIT0();
            __syncthreads();
            const int u = bid + MEAN_CTAS * j;
            const int b = u >> 10, z = (u >> 9) & 1, c = u & 511;
            float* dst = g_means + (((size_t)z * BB + b) * 160) * CHN + c;
            if (tid < 80) {
                float s = 0.f;
                const float4* r4 = reinterpret_cast<const float4*>(cur + tid * 80);
                #pragma unroll
                for (int w = 0; w < 20; ++w) { float4 v = r4[w]; s += v.x + v.y + v.z + v.w; }
                dst[(size_t)tid * CHN] = s * (1.f / 80.f);
            } else if (tid < 160) {
                const int w = tid - 80;
                float s = 0.f;
                #pragma unroll 8
                for (int h = 0; h < 80; ++h) s += cur[h * 80 + w];
                dst[(size_t)tid * CHN] = s * (1.f / 80.f);
            }
            signal(&g_sync[b]);     // fence + barrier + t0 atomic
        }

        // ======== phase Y: yz (units u = bid + 64*j, j < 5) ========
        {
            float* w_s = dynsmem;              // 256*33
            float* x_s = dynsmem + 256 * 33;   // 8*256
            for (int j = 0; j < 5; ++j) {
                const int u = bid + MEAN_CTAS * j;
                const int b = u / 40;
                const int r = u % 40;
                const int z = r / 20;
                const int p0 = (r % 20) * 8;
                spin_until(&g_sync[b], 1024);
                const float* wsrc = z ? w_t1 : w_r1;
                const float* xbase = g_means + (((size_t)z * BB + b) * 160 + p0) * CHN;
                const int cr = tid & 31;
                const int pl = tid >> 5;
                float acc = 0.f;
                for (int half = 0; half < 2; ++half) {
                    const int c0 = half * 256;
                    for (int i = tid; i < 32 * 256; i += 256) {
                        const int cc = i & 255, crr = i >> 8;
                        w_s[cc * 33 + crr] = wsrc[crr * CHN + c0 + cc];
                    }
                    for (int i = tid; i < 8 * 256; i += 256) {
                        const int ppl = i >> 8, cc = i & 255;
                        x_s[ppl * 256 + cc] = xbase[(size_t)ppl * CHN + c0 + cc];
                    }
                    __syncthreads();
                    #pragma unroll 8
                    for (int cc = 0; cc < 256; ++cc)
                        acc += w_s[cc * 33 + cr] * x_s[pl * 256 + cc];
                    __syncthreads();
                }
                float s = acc;
                if (z == 0) {
                    const float sc = bn_g[cr] * rsqrtf(bn_v[cr] + 1e-5f);
                    s = s * sc + (bn_b[cr] - bn_m[cr] * sc);
                }
                s = fmaxf(s, 0.f);
                g_yz[(((size_t)z * BB + b) * CR + cr) * 160 + p0 + pl] = s;
                signal(&g_sync[8 + b]);
            }
        }

        // ======== phase S: gates (units u = bid + 64*j, j < 4) ========
        {
            float* ys  = dynsmem;              // 32*80
            float* wch = dynsmem + CR * 80;    // 64*33
            for (int j = 0; j < 4; ++j) {
                const int u = bid + MEAN_CTAS * j;
                const int b = u >> 5;
                const int r = u & 31;
                const int a = r >> 3;
                const int oc = r & 7;
                spin_until(&g_sync[8 + b], 40);
                const float* wp = (a == 0) ? w_fh1 : (a == 1) ? w_fw1 : (a == 2) ? w_fh2 : w_fw2;
                const int z = a >> 1;
                const int off = (a & 1) * 80;
                for (int i = tid; i < CR * 80; i += 256) {
                    const int cr = i / 80, p = i % 80;
                    ys[cr * 80 + p] = g_yz[(((size_t)z * BB + b) * CR + cr) * 160 + off + p];
                }
                for (int i = tid; i < 64 * 32; i += 256) {
                    const int ol = i >> 5, cr = i & 31;
                    wch[ol * 33 + cr] = wp[(oc * 64 + ol) * CR + cr];
                }
                __syncthreads();
                const int ol = tid >> 2;
                const int hg = (tid & 3) * 20;
                float* dst = g_s + (((size_t)a * BB + b) * CHN + oc * 64 + ol) * 80;
                #pragma unroll
                for (int jj = 0; jj < 20; ++jj) {
                    const int h = hg + jj;
                    float s = 0.f;
                    #pragma unroll
                    for (int cr = 0; cr < CR; ++cr) s += wch[ol * 33 + cr] * ys[cr * 80 + h];
                    dst[h] = 1.f / (1.f + __expf(-s));
                }
                signal(&g_sync[16 + b]);
            }
        }
    } else if (bid < MEAN_CTAS + WREP_CTAS) {
        // ======== phase W: W repack (one unit per CTA) ========
        const int blk = bid - MEAN_CTAS;       // 0..127 = o_blk*32 + kt
        const int o_blk = blk >> 5, kt = blk & 31;
        #pragma unroll
        for (int i = 0; i < 4; ++i) {
            const int gid = tid + i * 256;
            const int lane = gid & 31;
            const int mi = (gid >> 5) & 3;
            const int wm = (gid >> 7) & 1;
            const int kk = (gid >> 8) & 3;
            const int R  = o_blk * 128 + wm * 64 + mi * 16 + (lane >> 2);
            const int Ka = kt * 32 + kk * 8 + (lane & 3);
            uint4 o;
            o.x = f2tf32(w_fuse[(size_t)R * 1024 + Ka]);
            o.y = f2tf32(w_fuse[(size_t)(R + 8) * 1024 + Ka]);
            o.z = f2tf32(w_fuse[(size_t)R * 1024 + Ka + 4]);
            o.w = f2tf32(w_fuse[(size_t)(R + 8) * 1024 + Ka + 4]);
            reinterpret_cast<uint4*>(g_wr)[(size_t)blk * 1024 + gid] = o;
        }
        signal(&g_sync[25]);
    }

    // ======== gemm tile loop (all CTAs) ========
    spin_until(&g_sync[25], WREP_CTAS);

    const int lane = tid & 31;
    const int warp = tid >> 5;
    const int wm = warp >> 2;
    const int wn = warp & 3;

    while (true) {
        __syncthreads();
        if (tid == 0) s_ticket = atomicAdd(&g_sync[24], 1);
        __syncthreads();
        const int tkt = s_ticket;
        if (tkt >= GEMM_TILES) break;

        const int b = tkt / 200;
        const int rr = tkt % 200;
        const int o_blk = rr / 50;
        const int p0 = (rr % 50) * BN;

        const float* rgbB = rgb + (size_t)b * CHN * HW;
        const float* tB   = t   + (size_t)b * CHN * HW;
        const float* wbase = g_wr + (size_t)o_blk * 32 * A_STAGE_FLOATS;

        float acc[4][4][4];
        #pragma unroll
        for (int i = 0; i < 4; ++i)
            #pragma unroll
            for (int j = 0; j < 4; ++j)
                #pragma unroll
                for (int e = 0; e < 4; ++e) acc[i][j][e] = 0.f;

        auto issue = [&](int stage, int kt) {
            const int k0 = kt * BK;
            const float* xb = (k0 < CHN) ? rgbB : tB;
            const int krow = k0 & (CHN - 1);
            float* As = dynsmem + stage * STAGE_FLOATS;
            float* Xs = As + A_STAGE_FLOATS;
            const float* asrc = wbase + (size_t)kt * A_STAGE_FLOATS;
            #pragma unroll
            for (int ps = 0; ps < 4; ++ps) {
                const int off = (tid + ps * 256) * 4;
                unsigned d = (unsigned)__cvta_generic_to_shared(&As[off]);
                CP_ASYNC16(d, asrc + off);
            }
            #pragma unroll
            for (int ps = 0; ps < 4; ++ps) {
                const int row = (tid >> 5) + ps * 8;
                const int cq  = (tid & 31) * 4;
                unsigned d = (unsigned)__cvta_generic_to_shared(&Xs[row * XS_STRIDE + cq]);
                CP_ASYNC16(d, xb + (size_t)(krow + row) * HW + p0 + cq);
            }
        };

        issue(0, 0); CP_COMMIT();
        issue(1, 1); CP_COMMIT();

        for (int kt = 0; kt < 1024 / BK; ++kt) {
            CP_WAIT1();
            __syncthreads();
            if (kt + 2 < 1024 / BK) issue((kt + 2) % NSTAGE, kt + 2);
            CP_COMMIT();

            const float* As = dynsmem + (kt % NSTAGE) * STAGE_FLOATS;
            const float* Xs = As + A_STAGE_FLOATS;
            const uint4* a4 = reinterpret_cast<const uint4*>(As);

            #pragma unroll
            for (int kk = 0; kk < 4; ++kk) {
                uint4 av[4];
                #pragma unroll
                for (int mi = 0; mi < 4; ++mi)
                    av[mi] = a4[((kk * 2 + wm) * 4 + mi) * 32 + lane];
                unsigned bfr[4][2];
                const int ka = kk * 8 + (lane & 3);
                const int cb = wn * 32 + (lane >> 2);
                #pragma unroll
                for (int ni = 0; ni < 4; ++ni) {
                    const float* bp = &Xs[ka * XS_STRIDE + cb + ni * 8];
                    bfr[ni][0] = f2tf32(bp[0]);
                    bfr[ni][1] = f2tf32(bp[4 * XS_STRIDE]);
                }
                #pragma unroll
                for (int mi = 0; mi < 4; ++mi)
                    #pragma unroll
                    for (int ni = 0; ni < 4; ++ni)
                        mma_tf32(acc[mi][ni], av[mi].x, av[mi].y, av[mi].z, av[mi].w,
                                 bfr[ni][0], bfr[ni][1]);
            }
        }
        CP_WAIT0();

        // per-batch gate, then epilogue
        spin_until(&g_sync[16 + b], 32);

        const float* sh1 = g_s + (((size_t)0 * BB + b) * CHN) * 80;
        const float* sw1 = g_s + (((size_t)1 * BB + b) * CHN) * 80;
        const float* sh2 = g_s + (((size_t)2 * BB + b) * CHN) * 80;
        const float* sw2 = g_s + (((size_t)3 * BB + b) * CHN) * 80;
        float* outB = out + (size_t)b * CHN * HW;
        const int o0 = o_blk * BM;

        #pragma unroll
        for (int mi = 0; mi < 4; ++mi) {
            const int r = o0 + wm * 64 + mi * 16 + (lane >> 2);
            #pragma unroll
            for (int ni = 0; ni < 4; ++ni) {
                const int pc = p0 + wn * 32 + ni * 8 + 2 * (lane & 3);
                const int h = pc / 80;
                const int w = pc - h * 80;
                #pragma unroll
                for (int half = 0; half < 2; ++half) {
                    const int o = r + half * 8;
                    const float sh1v = sh1[o * 80 + h];
                    const float sh2v = sh2[o * 80 + h];
                    const float g0 = sh1v * sw1[o * 80 + w]     + sh2v * sw2[o * 80 + w];
                    const float g1 = sh1v * sw1[o * 80 + w + 1] + sh2v * sw2[o * 80 + w + 1];
                    float2 v;
                    v.x = acc[mi][ni][half * 2 + 0] * g0;
                    v.y = acc[mi][ni][half * 2 + 1] * g1;
                    *reinterpret_cast<float2*>(outB + (size_t)o * HW + pc) = v;
                }
            }
        }
    }
}

// ---------------- launch ----------------
extern "C" void kernel_launch(void* const* d_in, const int* in_sizes, int n_in,
                              void* d_out, int out_size) {
    const float* rgb    = (const float*)d_in[0];
    const float* t      = (const float*)d_in[1];
    const float* w_fuse = (const float*)d_in[2];
    const float* w_r1   = (const float*)d_in[3];
    const float* w_t1   = (const float*)d_in[4];
    const float* w_fh1  = (const float*)d_in[5];
    const float* w_fw1  = (const float*)d_in[6];
    const float* w_fh2  = (const float*)d_in[7];
    const float* w_fw2  = (const float*)d_in[8];
    const float* bn_g   = (const float*)d_in[9];
    const float* bn_b   = (const float*)d_in[10];
    const float* bn_m   = (const float*)d_in[11];
    const float* bn_v   = (const float*)d_in[12];
    float* out = (float*)d_out;

    int dev = 0, nsm = 148;
    cudaGetDevice(&dev);
    cudaDeviceGetAttribute(&nsm, cudaDevAttrMultiProcessorCount, dev);
    const int grid = 2 * nsm;   // all CTAs co-resident (2 CTAs/SM guaranteed by regs+smem)

    cudaFuncSetAttribute(mega_kernel, cudaFuncAttributeMaxDynamicSharedMemorySize, GEMM_SMEM);

    zero_kernel<<<1, 32>>>();
    mega_kernel<<<grid, 256, GEMM_SMEM>>>(
        rgb, t, w_fuse, w_r1, w_t1, bn_g, bn_b, bn_m, bn_v,
        w_fh1, w_fw1, w_fh2, w_fw2, out);
}

// round 11
// speedup vs baseline: 1.6566x; 1.6566x over previous
#include <cuda_runtime.h>
#include <cuda_bf16.h>
#include <cstdint>

// Problem constants
#define BB 8
#define CHN 512
#define HH 80
#define WW 80
#define HW 6400
#define CR 32

// ---------------- device scratch ----------------
__device__ float g_means[2 * BB * 160 * CHN];   // [z][b][p][c]
__device__ float g_yz[2 * BB * CR * 160];       // [z][b][cr][160]
__device__ float g_s[4 * BB * CHN * 80];        // [a][b][o][80]
// W repacked to fragment-order tf32: [o_blk][kt][kk][wm][mi][lane][4]
__device__ float g_wr[CHN * 1024];

// ---------------- helpers ----------------
__device__ __forceinline__ unsigned f2tf32(float x) {
    unsigned u;
    asm("cvt.rna.tf32.f32 %0, %1;" : "=r"(u) : "f"(x));
    return u;
}

__device__ __forceinline__ void mma_tf32(float d[4], const unsigned a0, const unsigned a1,
                                         const unsigned a2, const unsigned a3,
                                         const unsigned b0, const unsigned b1) {
    asm volatile(
        "mma.sync.aligned.m16n8k8.row.col.f32.tf32.tf32.f32 "
        "{%0,%1,%2,%3}, {%4,%5,%6,%7}, {%8,%9}, {%0,%1,%2,%3};\n"
        : "+f"(d[0]), "+f"(d[1]), "+f"(d[2]), "+f"(d[3])
        : "r"(a0), "r"(a1), "r"(a2), "r"(a3), "r"(b0), "r"(b1));
}

#define CP_ASYNC16(dst_u32, src_ptr) \
    asm volatile("cp.async.cg.shared.global [%0], [%1], 16;\n" :: "r"(dst_u32), "l"(src_ptr))
#define CP_COMMIT() asm volatile("cp.async.commit_group;\n" ::)
#define CP_WAIT1()  asm volatile("cp.async.wait_group 1;\n" ::)

// ---------------- kernel W-repack: fragment-order tf32 ----------------
__global__ void wrepack_kernel(const float* __restrict__ w) {
    const int blk = blockIdx.x;          // o_blk*32 + kt
    const int o_blk = blk >> 5, kt = blk & 31;
    const int tid = threadIdx.x;
    #pragma unroll
    for (int i = 0; i < 4; ++i) {
        const int gid = tid + i * 256;
        const int lane = gid & 31;
        const int mi = (gid >> 5) & 3;
        const int wm = (gid >> 7) & 1;
        const int kk = (gid >> 8) & 3;
        const int R  = o_blk * 128 + wm * 64 + mi * 16 + (lane >> 2);
        const int Ka = kt * 32 + kk * 8 + (lane & 3);
        uint4 o;
        o.x = f2tf32(w[(size_t)R * 1024 + Ka]);
        o.y = f2tf32(w[(size_t)(R + 8) * 1024 + Ka]);
        o.z = f2tf32(w[(size_t)R * 1024 + Ka + 4]);
        o.w = f2tf32(w[(size_t)(R + 8) * 1024 + Ka + 4]);
        reinterpret_cast<uint4*>(g_wr)[(size_t)blk * 1024 + gid] = o;
    }
}

// ---------------- kernel A: H-means and W-means of rgb and t ----------------
__global__ void mean_kernel(const float* __restrict__ rgb, const float* __restrict__ t) {
    const int c = blockIdx.x;
    const int b = blockIdx.y;
    const int z = blockIdx.z;
    const float* src = (z ? t : rgb) + ((size_t)(b * CHN) + c) * HW;
    __shared__ float sm[HW];
    const int tid = threadIdx.x;
    const float4* src4 = reinterpret_cast<const float4*>(src);
    float4* sm4 = reinterpret_cast<float4*>(sm);
    for (int i = tid; i < HW / 4; i += 256) sm4[i] = src4[i];
    __syncthreads();
    float* dst = g_means + (((size_t)z * BB + b) * 160) * CHN + c;
    if (tid < 80) {
        float s = 0.f;
        const float4* r4 = reinterpret_cast<const float4*>(sm + tid * 80);
        #pragma unroll
        for (int w = 0; w < 20; ++w) { float4 v = r4[w]; s += v.x + v.y + v.z + v.w; }
        dst[(size_t)tid * CHN] = s * (1.f / 80.f);
    } else if (tid < 160) {
        const int w = tid - 80;
        float s = 0.f;
        #pragma unroll 8
        for (int h = 0; h < 80; ++h) s += sm[h * 80 + w];
        dst[(size_t)(tid) * CHN] = s * (1.f / 80.f);
    }
}

// ---------------- kernel B1: tiny GEMM + BN/relu ----------------
__global__ void yz_kernel(const float* __restrict__ w_r1, const float* __restrict__ w_t1,
                          const float* __restrict__ bn_g, const float* __restrict__ bn_b,
                          const float* __restrict__ bn_m, const float* __restrict__ bn_v) {
    const int p0 = blockIdx.x * 8;
    const int b  = blockIdx.y;
    const int z  = blockIdx.z;
    const float* wsrc = z ? w_t1 : w_r1;
    const float* xbase = g_means + (((size_t)z * BB + b) * 160 + p0) * CHN;

    __shared__ float w_s[256 * 33];
    __shared__ float x_s[8 * 256];

    const int tid = threadIdx.x;
    const int cr = tid & 31;
    const int pl = tid >> 5;
    float acc = 0.f;

    for (int half = 0; half < 2; ++half) {
        if (half) __syncthreads();
        const int c0 = half * 256;
        for (int j = tid; j < 32 * 256; j += 256) {
            const int cc = j & 255, crr = j >> 8;
            w_s[cc * 33 + crr] = wsrc[crr * CHN + c0 + cc];
        }
        for (int j = tid; j < 8 * 256; j += 256) {
            const int ppl = j >> 8, cc = j & 255;
            x_s[ppl * 256 + cc] = xbase[(size_t)ppl * CHN + c0 + cc];
        }
        __syncthreads();
        #pragma unroll 8
        for (int cc = 0; cc < 256; ++cc)
            acc += w_s[cc * 33 + cr] * x_s[pl * 256 + cc];
    }

    float s = acc;
    if (z == 0) {
        const float sc = bn_g[cr] * rsqrtf(bn_v[cr] + 1e-5f);
        s = s * sc + (bn_b[cr] - bn_m[cr] * sc);
    }
    s = fmaxf(s, 0.f);
    g_yz[(((size_t)z * BB + b) * CR + cr) * 160 + p0 + pl] = s;
}

// ---------------- kernel B2: sigmoid gates ----------------
__global__ void s_kernel(const float* __restrict__ w_fh1, const float* __restrict__ w_fw1,
                         const float* __restrict__ w_fh2, const float* __restrict__ w_fw2) {
    const int a  = blockIdx.x;
    const int b  = blockIdx.y;
    const int oc = blockIdx.z;
    const float* wp = (a == 0) ? w_fh1 : (a == 1) ? w_fw1 : (a == 2) ? w_fh2 : w_fw2;
    const int z = a >> 1;
    const int off = (a & 1) * 80;

    __shared__ float ys[CR][80];
    __shared__ float wch[64][33];

    const int tid = threadIdx.x;
    for (int i = tid; i < CR * 80; i += 256) {
        const int cr = i / 80, p = i % 80;
        ys[cr][p] = g_yz[(((size_t)z * BB + b) * CR + cr) * 160 + off + p];
    }
    for (int i = tid; i < 64 * 32; i += 256) {
        const int ol = i >> 5, cr = i & 31;
        wch[ol][cr] = wp[(oc * 64 + ol) * CR + cr];
    }
    __syncthreads();

    const int ol = tid >> 2;
    const int hg = (tid & 3) * 20;
    float* dst = g_s + (((size_t)a * BB + b) * CHN + oc * 64 + ol) * 80;
    #pragma unroll
    for (int j = 0; j < 20; ++j) {
        const int h = hg + j;
        float s = 0.f;
        #pragma unroll
        for (int cr = 0; cr < CR; ++cr) s += wch[ol][cr] * ys[cr][h];
        dst[h] = 1.f / (1.f + __expf(-s));
    }
}

// ---------------- kernel C: tf32 mma.sync GEMM, 4 warps, 64x64 warp tile ----------------
#define BM 128
#define BN 128
#define BK 32
#define A_STAGE_FLOATS 4096               // 128x32 fragment-order
#define XS_STRIDE 136
#define X_STAGE_FLOATS (BK * XS_STRIDE)   // 4352
#define STAGE_FLOATS (A_STAGE_FLOATS + X_STAGE_FLOATS)  // 8448
#define NSTAGE 3
#define GEMM_SMEM (NSTAGE * STAGE_FLOATS * 4)           // 101376 bytes

__global__ __launch_bounds__(128, 2)
void gemm_kernel(const float* __restrict__ rgb, const float* __restrict__ t,
                 float* __restrict__ out) {
    extern __shared__ float dynsmem[];

    const int b  = blockIdx.z;
    const int o_blk = blockIdx.y;
    const int o0 = o_blk * BM;
    const int p0 = blockIdx.x * BN;
    const int tid  = threadIdx.x;
    const int lane = tid & 31;
    const int warp = tid >> 5;     // 0..3
    const int wm = warp >> 1;      // 0..1  (64 rows)
    const int wn = warp & 1;       // 0..1  (64 cols)

    const float* rgbB = rgb + (size_t)b * CHN * HW;
    const float* tB   = t   + (size_t)b * CHN * HW;
    const float* wbase = g_wr + (size_t)o_blk * 32 * A_STAGE_FLOATS;

    float acc[4][8][4];
    #pragma unroll
    for (int i = 0; i < 4; ++i)
        #pragma unroll
        for (int j = 0; j < 8; ++j)
            #pragma unroll
            for (int e = 0; e < 4; ++e) acc[i][j][e] = 0.f;

    auto issue = [&](int stage, int kt) {
        const int k0 = kt * BK;
        const float* xb = (k0 < CHN) ? rgbB : tB;
        const int krow = k0 & (CHN - 1);
        float* As = dynsmem + stage * STAGE_FLOATS;
        float* Xs = As + A_STAGE_FLOATS;
        const float* asrc = wbase + (size_t)kt * A_STAGE_FLOATS;
        // A: linear 16KB copy (1024 uint4 over 128 threads)
        #pragma unroll
        for (int ps = 0; ps < 8; ++ps) {
            const int off = (tid + ps * 128) * 4;
            unsigned d = (unsigned)__cvta_generic_to_shared(&As[off]);
            CP_ASYNC16(d, asrc + off);
        }
        // X tile: 32 rows x 128 cols
        #pragma unroll
        for (int ps = 0; ps < 8; ++ps) {
            const int row = (tid >> 5) + ps * 4;
            const int cq  = (tid & 31) * 4;
            unsigned d = (unsigned)__cvta_generic_to_shared(&Xs[row * XS_STRIDE + cq]);
            CP_ASYNC16(d, xb + (size_t)(krow + row) * HW + p0 + cq);
        }
    };

    issue(0, 0); CP_COMMIT();
    issue(1, 1); CP_COMMIT();

    for (int kt = 0; kt < 1024 / BK; ++kt) {
        CP_WAIT1();
        __syncthreads();
        if (kt + 2 < 1024 / BK) issue((kt + 2) % NSTAGE, kt + 2);
        CP_COMMIT();

        const float* As = dynsmem + (kt % NSTAGE) * STAGE_FLOATS;
        const float* Xs = As + A_STAGE_FLOATS;
        const uint4* a4 = reinterpret_cast<const uint4*>(As);

        #pragma unroll
        for (int kk = 0; kk < 4; ++kk) {
            uint4 av[4];
            #pragma unroll
            for (int mi = 0; mi < 4; ++mi)
                av[mi] = a4[((kk * 2 + wm) * 4 + mi) * 32 + lane];
            unsigned bfr[8][2];
            const int ka = kk * 8 + (lane & 3);
            const int cb = wn * 64 + (lane >> 2);
            #pragma unroll
            for (int ni = 0; ni < 8; ++ni) {
                const float* bp = &Xs[ka * XS_STRIDE + cb + ni * 8];
                bfr[ni][0] = f2tf32(bp[0]);
                bfr[ni][1] = f2tf32(bp[4 * XS_STRIDE]);
            }
            #pragma unroll
            for (int mi = 0; mi < 4; ++mi)
                #pragma unroll
                for (int ni = 0; ni < 8; ++ni)
                    mma_tf32(acc[mi][ni], av[mi].x, av[mi].y, av[mi].z, av[mi].w,
                             bfr[ni][0], bfr[ni][1]);
        }
    }

    // Epilogue: gate and store
    const float* sh1 = g_s + (((size_t)0 * BB + b) * CHN) * 80;
    const float* sw1 = g_s + (((size_t)1 * BB + b) * CHN) * 80;
    const float* sh2 = g_s + (((size_t)2 * BB + b) * CHN) * 80;
    const float* sw2 = g_s + (((size_t)3 * BB + b) * CHN) * 80;
    float* outB = out + (size_t)b * CHN * HW;

    #pragma unroll
    for (int mi = 0; mi < 4; ++mi) {
        const int r = o0 + wm * 64 + mi * 16 + (lane >> 2);
        #pragma unroll
        for (int ni = 0; ni < 8; ++ni) {
            const int pc = p0 + wn * 64 + ni * 8 + 2 * (lane & 3);
            const int h = pc / 80;
            const int w = pc - h * 80;
            #pragma unroll
            for (int half = 0; half < 2; ++half) {
                const int o = r + half * 8;
                const float sh1v = sh1[o * 80 + h];
                const float sh2v = sh2[o * 80 + h];
                const float g0 = sh1v * sw1[o * 80 + w]     + sh2v * sw2[o * 80 + w];
                const float g1 = sh1v * sw1[o * 80 + w + 1] + sh2v * sw2[o * 80 + w + 1];
                float2 v;
                v.x = acc[mi][ni][half * 2 + 0] * g0;
                v.y = acc[mi][ni][half * 2 + 1] * g1;
                *reinterpret_cast<float2*>(outB + (size_t)o * HW + pc) = v;
            }
        }
    }
}

// ---------------- launch ----------------
extern "C" void kernel_launch(void* const* d_in, const int* in_sizes, int n_in,
                              void* d_out, int out_size) {
    const float* rgb    = (const float*)d_in[0];
    const float* t      = (const float*)d_in[1];
    const float* w_fuse = (const float*)d_in[2];
    const float* w_r1   = (const float*)d_in[3];
    const float* w_t1   = (const float*)d_in[4];
    const float* w_fh1  = (const float*)d_in[5];
    const float* w_fw1  = (const float*)d_in[6];
    const float* w_fh2  = (const float*)d_in[7];
    const float* w_fw2  = (const float*)d_in[8];
    const float* bn_g   = (const float*)d_in[9];
    const float* bn_b   = (const float*)d_in[10];
    const float* bn_m   = (const float*)d_in[11];
    const float* bn_v   = (const float*)d_in[12];
    float* out = (float*)d_out;

    cudaFuncSetAttribute(gemm_kernel, cudaFuncAttributeMaxDynamicSharedMemorySize, GEMM_SMEM);

    wrepack_kernel<<<128, 256>>>(w_fuse);
    mean_kernel<<<dim3(CHN, BB, 2), 256>>>(rgb, t);
    yz_kernel<<<dim3(20, BB, 2), 256>>>(w_r1, w_t1, bn_g, bn_b, bn_m, bn_v);
    s_kernel<<<dim3(4, BB, 8), 256>>>(w_fh1, w_fw1, w_fh2, w_fw2);
    gemm_kernel<<<dim3(HW / BN, CHN / BM, BB), 128, GEMM_SMEM>>>(rgb, t, out);
}

// round 13
// speedup vs baseline: 1.6930x; 1.0220x over previous
#include <cuda_runtime.h>
#include <cuda_bf16.h>
#include <cstdint>

// Problem constants
#define BB 8
#define CHN 512
#define HH 80
#define WW 80
#define HW 6400
#define CR 32

// ---------------- device scratch ----------------
__device__ float g_means[2 * BB * 160 * CHN];   // [z][b][p][c]
__device__ float g_yz[2 * BB * CR * 160];       // [z][b][cr][160]
__device__ float g_s[4 * BB * CHN * 80];        // [a][b][o][80]
// W repacked to fragment-order tf32: [o_blk][kt][kk][wm][mi][lane][4]
__device__ float g_wr[CHN * 1024];

// ---------------- helpers ----------------
__device__ __forceinline__ unsigned f2tf32(float x) {
    unsigned u;
    asm("cvt.rna.tf32.f32 %0, %1;" : "=r"(u) : "f"(x));
    return u;
}

__device__ __forceinline__ void mma_tf32(float d[4], const unsigned a0, const unsigned a1,
                                         const unsigned a2, const unsigned a3,
                                         const unsigned b0, const unsigned b1) {
    asm volatile(
        "mma.sync.aligned.m16n8k8.row.col.f32.tf32.tf32.f32 "
        "{%0,%1,%2,%3}, {%4,%5,%6,%7}, {%8,%9}, {%0,%1,%2,%3};\n"
        : "+f"(d[0]), "+f"(d[1]), "+f"(d[2]), "+f"(d[3])
        : "r"(a0), "r"(a1), "r"(a2), "r"(a3), "r"(b0), "r"(b1));
}

#define CP_ASYNC16(dst_u32, src_ptr) \
    asm volatile("cp.async.cg.shared.global [%0], [%1], 16;\n" :: "r"(dst_u32), "l"(src_ptr))
#define CP_COMMIT() asm volatile("cp.async.commit_group;\n" ::)
#define CP_WAIT1()  asm volatile("cp.async.wait_group 1;\n" ::)
#define CP_WAIT0()  asm volatile("cp.async.wait_group 0;\n" ::)

// ---------------- kernel W-repack: fragment-order tf32 ----------------
__global__ void wrepack_kernel(const float* __restrict__ w) {
    const int blk = blockIdx.x;          // o_blk*32 + kt
    const int o_blk = blk >> 5, kt = blk & 31;
    const int tid = threadIdx.x;
    #pragma unroll
    for (int i = 0; i < 4; ++i) {
        const int gid = tid + i * 256;
        const int lane = gid & 31;
        const int mi = (gid >> 5) & 3;
        const int wm = (gid >> 7) & 1;
        const int kk = (gid >> 8) & 3;
        const int R  = o_blk * 128 + wm * 64 + mi * 16 + (lane >> 2);
        const int Ka = kt * 32 + kk * 8 + (lane & 3);
        uint4 o;
        o.x = f2tf32(w[(size_t)R * 1024 + Ka]);
        o.y = f2tf32(w[(size_t)(R + 8) * 1024 + Ka]);
        o.z = f2tf32(w[(size_t)R * 1024 + Ka + 4]);
        o.w = f2tf32(w[(size_t)(R + 8) * 1024 + Ka + 4]);
        reinterpret_cast<uint4*>(g_wr)[(size_t)blk * 1024 + gid] = o;
    }
}

// ---------------- kernel A: H-means and W-means of rgb and t ----------------
__global__ void mean_kernel(const float* __restrict__ rgb, const float* __restrict__ t) {
    const int c = blockIdx.x;
    const int b = blockIdx.y;
    const int z = blockIdx.z;
    const float* src = (z ? t : rgb) + ((size_t)(b * CHN) + c) * HW;
    __shared__ float sm[HW];
    const int tid = threadIdx.x;
    const float4* src4 = reinterpret_cast<const float4*>(src);
    float4* sm4 = reinterpret_cast<float4*>(sm);
    for (int i = tid; i < HW / 4; i += 256) sm4[i] = src4[i];
    __syncthreads();
    float* dst = g_means + (((size_t)z * BB + b) * 160) * CHN + c;
    if (tid < 80) {
        float s = 0.f;
        const float4* r4 = reinterpret_cast<const float4*>(sm + tid * 80);
        #pragma unroll
        for (int w = 0; w < 20; ++w) { float4 v = r4[w]; s += v.x + v.y + v.z + v.w; }
        dst[(size_t)tid * CHN] = s * (1.f / 80.f);
    } else if (tid < 160) {
        const int w = tid - 80;
        float s = 0.f;
        #pragma unroll 8
        for (int h = 0; h < 80; ++h) s += sm[h * 80 + w];
        dst[(size_t)(tid) * CHN] = s * (1.f / 80.f);
    }
}

// ---------------- kernel B1: tiny GEMM + BN/relu ----------------
__global__ void yz_kernel(const float* __restrict__ w_r1, const float* __restrict__ w_t1,
                          const float* __restrict__ bn_g, const float* __restrict__ bn_b,
                          const float* __restrict__ bn_m, const float* __restrict__ bn_v) {
    const int p0 = blockIdx.x * 8;
    const int b  = blockIdx.y;
    const int z  = blockIdx.z;
    const float* wsrc = z ? w_t1 : w_r1;
    const float* xbase = g_means + (((size_t)z * BB + b) * 160 + p0) * CHN;

    __shared__ float w_s[256 * 33];
    __shared__ float x_s[8 * 256];

    const int tid = threadIdx.x;
    const int cr = tid & 31;
    const int pl = tid >> 5;
    float acc = 0.f;

    for (int half = 0; half < 2; ++half) {
        if (half) __syncthreads();
        const int c0 = half * 256;
        for (int j = tid; j < 32 * 256; j += 256) {
            const int cc = j & 255, crr = j >> 8;
            w_s[cc * 33 + crr] = wsrc[crr * CHN + c0 + cc];
        }
        for (int j = tid; j < 8 * 256; j += 256) {
            const int ppl = j >> 8, cc = j & 255;
            x_s[ppl * 256 + cc] = xbase[(size_t)ppl * CHN + c0 + cc];
        }
        __syncthreads();
        #pragma unroll 8
        for (int cc = 0; cc < 256; ++cc)
            acc += w_s[cc * 33 + cr] * x_s[pl * 256 + cc];
    }

    float s = acc;
    if (z == 0) {
        const float sc = bn_g[cr] * rsqrtf(bn_v[cr] + 1e-5f);
        s = s * sc + (bn_b[cr] - bn_m[cr] * sc);
    }
    s = fmaxf(s, 0.f);
    g_yz[(((size_t)z * BB + b) * CR + cr) * 160 + p0 + pl] = s;
}

// ---------------- kernel B2: sigmoid gates ----------------
__global__ void s_kernel(const float* __restrict__ w_fh1, const float* __restrict__ w_fw1,
                         const float* __restrict__ w_fh2, const float* __restrict__ w_fw2) {
    const int a  = blockIdx.x;
    const int b  = blockIdx.y;
    const int oc = blockIdx.z;
    const float* wp = (a == 0) ? w_fh1 : (a == 1) ? w_fw1 : (a == 2) ? w_fh2 : w_fw2;
    const int z = a >> 1;
    const int off = (a & 1) * 80;

    __shared__ float ys[CR][80];
    __shared__ float wch[64][33];

    const int tid = threadIdx.x;
    for (int i = tid; i < CR * 80; i += 256) {
        const int cr = i / 80, p = i % 80;
        ys[cr][p] = g_yz[(((size_t)z * BB + b) * CR + cr) * 160 + off + p];
    }
    for (int i = tid; i < 64 * 32; i += 256) {
        const int ol = i >> 5, cr = i & 31;
        wch[ol][cr] = wp[(oc * 64 + ol) * CR + cr];
    }
    __syncthreads();

    const int ol = tid >> 2;
    const int hg = (tid & 3) * 20;
    float* dst = g_s + (((size_t)a * BB + b) * CHN + oc * 64 + ol) * 80;
    #pragma unroll
    for (int j = 0; j < 20; ++j) {
        const int h = hg + j;
        float s = 0.f;
        #pragma unroll
        for (int cr = 0; cr < CR; ++cr) s += wch[ol][cr] * ys[cr][h];
        dst[h] = 1.f / (1.f + __expf(-s));
    }
}

// ---------------- kernel C: tf32 mma.sync GEMM, 4 warps 64x64, reg double-buffer (race-free) ----------------
#define BM 128
#define BN 128
#define BK 32
#define A_STAGE_FLOATS 4096               // 128x32 fragment-order
#define XS_STRIDE 136
#define X_STAGE_FLOATS (BK * XS_STRIDE)   // 4352
#define STAGE_FLOATS (A_STAGE_FLOATS + X_STAGE_FLOATS)  // 8448
#define NSTAGE 3
#define GEMM_SMEM (NSTAGE * STAGE_FLOATS * 4)           // 101376 bytes
#define NKT 32

struct Frag {
    uint4 a[4];
    unsigned b[8][2];
};

__global__ __launch_bounds__(128, 2)
void gemm_kernel(const float* __restrict__ rgb, const float* __restrict__ t,
                 float* __restrict__ out) {
    extern __shared__ float dynsmem[];

    const int b  = blockIdx.z;
    const int o_blk = blockIdx.y;
    const int o0 = o_blk * BM;
    const int p0 = blockIdx.x * BN;
    const int tid  = threadIdx.x;
    const int lane = tid & 31;
    const int warp = tid >> 5;     // 0..3
    const int wm = warp >> 1;      // 0..1  (64 rows)
    const int wn = warp & 1;       // 0..1  (64 cols)

    const float* rgbB = rgb + (size_t)b * CHN * HW;
    const float* tB   = t   + (size_t)b * CHN * HW;
    const float* wbase = g_wr + (size_t)o_blk * 32 * A_STAGE_FLOATS;

    float acc[4][8][4];
    #pragma unroll
    for (int i = 0; i < 4; ++i)
        #pragma unroll
        for (int j = 0; j < 8; ++j)
            #pragma unroll
            for (int e = 0; e < 4; ++e) acc[i][j][e] = 0.f;

    auto issue = [&](int stage, int kt) {
        const int k0 = kt * BK;
        const float* xb = (k0 < CHN) ? rgbB : tB;
        const int krow = k0 & (CHN - 1);
        float* As = dynsmem + stage * STAGE_FLOATS;
        float* Xs = As + A_STAGE_FLOATS;
        const float* asrc = wbase + (size_t)kt * A_STAGE_FLOATS;
        #pragma unroll
        for (int ps = 0; ps < 8; ++ps) {
            const int off = (tid + ps * 128) * 4;
            unsigned d = (unsigned)__cvta_generic_to_shared(&As[off]);
            CP_ASYNC16(d, asrc + off);
        }
        #pragma unroll
        for (int ps = 0; ps < 8; ++ps) {
            const int row = (tid >> 5) + ps * 4;
            const int cq  = (tid & 31) * 4;
            unsigned d = (unsigned)__cvta_generic_to_shared(&Xs[row * XS_STRIDE + cq]);
            CP_ASYNC16(d, xb + (size_t)(krow + row) * HW + p0 + cq);
        }
    };

    auto load_frag = [&](Frag& f, const float* As, int kk) {
        const uint4* a4 = reinterpret_cast<const uint4*>(As);
        const float* Xs = As + A_STAGE_FLOATS;
        #pragma unroll
        for (int mi = 0; mi < 4; ++mi)
            f.a[mi] = a4[((kk * 2 + wm) * 4 + mi) * 32 + lane];
        const int ka = kk * 8 + (lane & 3);
        const int cb = wn * 64 + (lane >> 2);
        #pragma unroll
        for (int ni = 0; ni < 8; ++ni) {
            const float* bp = &Xs[ka * XS_STRIDE + cb + ni * 8];
            f.b[ni][0] = f2tf32(bp[0]);
            f.b[ni][1] = f2tf32(bp[4 * XS_STRIDE]);
        }
    };

    auto mma_all = [&](const Frag& f) {
        #pragma unroll
        for (int mi = 0; mi < 4; ++mi)
            #pragma unroll
            for (int ni = 0; ni < 8; ++ni)
                mma_tf32(acc[mi][ni], f.a[mi].x, f.a[mi].y, f.a[mi].z, f.a[mi].w,
                         f.b[ni][0], f.b[ni][1]);
    };

    // prologue: stages 0 and 1 in flight; stage 0 visible after wait+sync
    issue(0, 0); CP_COMMIT();
    issue(1, 1); CP_COMMIT();
    CP_WAIT1();
    __syncthreads();

    Frag fr[2];
    load_frag(fr[0], dynsmem, 0);
    int cur = 0;

    for (int kt = 0; kt < NKT; ++kt) {
        // issue stage kt+2 (overwrites stage kt-1, whose reads finished before the
        // previous iteration's __syncthreads)
        if (kt + 2 < NKT) { issue((kt + 2) % NSTAGE, kt + 2); CP_COMMIT(); }

        const float* As = dynsmem + (kt % NSTAGE) * STAGE_FLOATS;

        // kk = 0..2: prefetch next kk's fragments, then compute current
        #pragma unroll
        for (int kk = 0; kk < 3; ++kk) {
            load_frag(fr[cur ^ 1], As, kk + 1);
            mma_all(fr[cur]);
            cur ^= 1;
        }

        // make stage kt+1 visible to ALL threads: own wait, then block-wide sync
        if (kt + 2 < NKT)      CP_WAIT1();   // pending {kt+1, kt+2} -> kt+1 arrived
        else if (kt + 1 < NKT) CP_WAIT0();   // pending {kt+1}      -> drain
        __syncthreads();

        // kk = 3 compute covers sync/issue exposure
        mma_all(fr[cur]);
        if (kt + 1 < NKT)
            load_frag(fr[cur ^ 1], dynsmem + ((kt + 1) % NSTAGE) * STAGE_FLOATS, 0);
        cur ^= 1;
    }

    // Epilogue: gate and store
    const float* sh1 = g_s + (((size_t)0 * BB + b) * CHN) * 80;
    const float* sw1 = g_s + (((size_t)1 * BB + b) * CHN) * 80;
    const float* sh2 = g_s + (((size_t)2 * BB + b) * CHN) * 80;
    const float* sw2 = g_s + (((size_t)3 * BB + b) * CHN) * 80;
    float* outB = out + (size_t)b * CHN * HW;

    #pragma unroll
    for (int mi = 0; mi < 4; ++mi) {
        const int r = o0 + wm * 64 + mi * 16 + (lane >> 2);
        #pragma unroll
        for (int ni = 0; ni < 8; ++ni) {
            const int pc = p0 + wn * 64 + ni * 8 + 2 * (lane & 3);
            const int h = pc / 80;
            const int w = pc - h * 80;
            #pragma unroll
            for (int half = 0; half < 2; ++half) {
                const int o = r + half * 8;
                const float sh1v = sh1[o * 80 + h];
                const float sh2v = sh2[o * 80 + h];
                const float g0 = sh1v * sw1[o * 80 + w]     + sh2v * sw2[o * 80 + w];
                const float g1 = sh1v * sw1[o * 80 + w + 1] + sh2v * sw2[o * 80 + w + 1];
                float2 v;
                v.x = acc[mi][ni][half * 2 + 0] * g0;
                v.y = acc[mi][ni][half * 2 + 1] * g1;
                *reinterpret_cast<float2*>(outB + (size_t)o * HW + pc) = v;
            }
        }
    }
}

// ---------------- launch ----------------
extern "C" void kernel_launch(void* const* d_in, const int* in_sizes, int n_in,
                              void* d_out, int out_size) {
    const float* rgb    = (const float*)d_in[0];
    const float* t      = (const float*)d_in[1];
    const float* w_fuse = (const float*)d_in[2];
    const float* w_r1   = (const float*)d_in[3];
    const float* w_t1   = (const float*)d_in[4];
    const float* w_fh1  = (const float*)d_in[5];
    const float* w_fw1  = (const float*)d_in[6];
    const float* w_fh2  = (const float*)d_in[7];
    const float* w_fw2  = (const float*)d_in[8];
    const float* bn_g   = (const float*)d_in[9];
    const float* bn_b   = (const float*)d_in[10];
    const float* bn_m   = (const float*)d_in[11];
    const float* bn_v   = (const float*)d_in[12];
    float* out = (float*)d_out;

    cudaFuncSetAttribute(gemm_kernel, cudaFuncAttributeMaxDynamicSharedMemorySize, GEMM_SMEM);

    wrepack_kernel<<<128, 256>>>(w_fuse);
    mean_kernel<<<dim3(CHN, BB, 2), 256>>>(rgb, t);
    yz_kernel<<<dim3(20, BB, 2), 256>>>(w_r1, w_t1, bn_g, bn_b, bn_m, bn_v);
    s_kernel<<<dim3(4, BB, 8), 256>>>(w_fh1, w_fw1, w_fh2, w_fw2);
    gemm_kernel<<<dim3(HW / BN, CHN / BM, BB), 128, GEMM_SMEM>>>(rgb, t, out);
}

// round 14
// speedup vs baseline: 1.7668x; 1.0435x over previous
#include <cuda_runtime.h>
#include <cuda_bf16.h>
#include <cstdint>

// Problem constants
#define BB 8
#define CHN 512
#define HH 80
#define WW 80
#define HW 6400
#define CR 32

// ---------------- device scratch ----------------
__device__ float g_means[2 * BB * 160 * CHN];   // [z][b][p][c]
__device__ float g_yz[2 * BB * CR * 160];       // [z][b][cr][160]
__device__ float g_s[4 * BB * CHN * 80];        // [a][b][o][80]
// W repacked to fragment-order tf32: [o_blk][kt][kk][wm][mi][lane][4]
__device__ float g_wr[CHN * 1024];

// ---------------- helpers ----------------
__device__ __forceinline__ unsigned f2tf32(float x) {
    unsigned u;
    asm("cvt.rna.tf32.f32 %0, %1;" : "=r"(u) : "f"(x));
    return u;
}

__device__ __forceinline__ void mma_tf32(float d[4], const unsigned a0, const unsigned a1,
                                         const unsigned a2, const unsigned a3,
                                         const unsigned b0, const unsigned b1) {
    asm volatile(
        "mma.sync.aligned.m16n8k8.row.col.f32.tf32.tf32.f32 "
        "{%0,%1,%2,%3}, {%4,%5,%6,%7}, {%8,%9}, {%0,%1,%2,%3};\n"
        : "+f"(d[0]), "+f"(d[1]), "+f"(d[2]), "+f"(d[3])
        : "r"(a0), "r"(a1), "r"(a2), "r"(a3), "r"(b0), "r"(b1));
}

#define CP_ASYNC16(dst_u32, src_ptr) \
    asm volatile("cp.async.cg.shared.global [%0], [%1], 16;\n" :: "r"(dst_u32), "l"(src_ptr))
#define CP_COMMIT() asm volatile("cp.async.commit_group;\n" ::)
#define CP_WAITG(n) asm volatile("cp.async.wait_group %0;\n" :: "n"(n))
#define CP_WAIT1()  asm volatile("cp.async.wait_group 1;\n" ::)
#define CP_WAIT0()  asm volatile("cp.async.wait_group 0;\n" ::)

// ---------------- kernel W-repack: fragment-order tf32 ----------------
__global__ void wrepack_kernel(const float* __restrict__ w) {
    const int blk = blockIdx.x;          // o_blk*32 + kt
    const int o_blk = blk >> 5, kt = blk & 31;
    const int tid = threadIdx.x;
    #pragma unroll
    for (int i = 0; i < 4; ++i) {
        const int gid = tid + i * 256;
        const int lane = gid & 31;
        const int mi = (gid >> 5) & 3;
        const int wm = (gid >> 7) & 1;
        const int kk = (gid >> 8) & 3;
        const int R  = o_blk * 128 + wm * 64 + mi * 16 + (lane >> 2);
        const int Ka = kt * 32 + kk * 8 + (lane & 3);
        uint4 o;
        o.x = f2tf32(w[(size_t)R * 1024 + Ka]);
        o.y = f2tf32(w[(size_t)(R + 8) * 1024 + Ka]);
        o.z = f2tf32(w[(size_t)R * 1024 + Ka + 4]);
        o.w = f2tf32(w[(size_t)(R + 8) * 1024 + Ka + 4]);
        reinterpret_cast<uint4*>(g_wr)[(size_t)blk * 1024 + gid] = o;
    }
}

// ---------------- kernel A: means, 4 channels per block, deep cp.async MLP ----------------
// grid (CHN/4, BB, 2), 256 threads, dynamic smem 4*HW*4 = 102400 B -> 2 CTAs/SM
#define MEAN_SMEM (4 * HW * 4)
__global__ __launch_bounds__(256, 2)
void mean_kernel(const float* __restrict__ rgb, const float* __restrict__ t) {
    extern __shared__ float sm[];
    const int c0 = blockIdx.x * 4;
    const int b = blockIdx.y;
    const int z = blockIdx.z;
    const int tid = threadIdx.x;
    const float* src = (z ? t : rgb) + ((size_t)(b * CHN) + c0) * HW;

    // issue all 4 channel loads up front (one commit group per channel)
    #pragma unroll
    for (int j = 0; j < 4; ++j) {
        const float* sj = src + (size_t)j * HW;
        float* bj = sm + j * HW;
        for (int i = tid; i < HW / 4; i += 256) {
            unsigned d = (unsigned)__cvta_generic_to_shared(bj + i * 4);
            CP_ASYNC16(d, sj + i * 4);
        }
        CP_COMMIT();
    }

    #pragma unroll
    for (int j = 0; j < 4; ++j) {
        switch (j) {
            case 0: CP_WAITG(3); break;
            case 1: CP_WAITG(2); break;
            case 2: CP_WAITG(1); break;
            default: CP_WAITG(0); break;
        }
        __syncthreads();
        const float* cur = sm + j * HW;
        float* dst = g_means + (((size_t)z * BB + b) * 160) * CHN + c0 + j;
        if (tid < 80) {
            float s = 0.f;
            const float4* r4 = reinterpret_cast<const float4*>(cur + tid * 80);
            #pragma unroll
            for (int w = 0; w < 20; ++w) { float4 v = r4[w]; s += v.x + v.y + v.z + v.w; }
            dst[(size_t)tid * CHN] = s * (1.f / 80.f);
        } else if (tid < 160) {
            const int w = tid - 80;
            float s = 0.f;
            #pragma unroll 8
            for (int h = 0; h < 80; ++h) s += cur[h * 80 + w];
            dst[(size_t)tid * CHN] = s * (1.f / 80.f);
        }
    }
}

// ---------------- kernel B1: tiny GEMM + BN/relu ----------------
__global__ void yz_kernel(const float* __restrict__ w_r1, const float* __restrict__ w_t1,
                          const float* __restrict__ bn_g, const float* __restrict__ bn_b,
                          const float* __restrict__ bn_m, const float* __restrict__ bn_v) {
    const int p0 = blockIdx.x * 8;
    const int b  = blockIdx.y;
    const int z  = blockIdx.z;
    const float* wsrc = z ? w_t1 : w_r1;
    const float* xbase = g_means + (((size_t)z * BB + b) * 160 + p0) * CHN;

    __shared__ float w_s[256 * 33];
    __shared__ float x_s[8 * 256];

    const int tid = threadIdx.x;
    const int cr = tid & 31;
    const int pl = tid >> 5;
    float acc = 0.f;

    for (int half = 0; half < 2; ++half) {
        if (half) __syncthreads();
        const int c0 = half * 256;
        for (int j = tid; j < 32 * 256; j += 256) {
            const int cc = j & 255, crr = j >> 8;
            w_s[cc * 33 + crr] = wsrc[crr * CHN + c0 + cc];
        }
        for (int j = tid; j < 8 * 256; j += 256) {
            const int ppl = j >> 8, cc = j & 255;
            x_s[ppl * 256 + cc] = xbase[(size_t)ppl * CHN + c0 + cc];
        }
        __syncthreads();
        #pragma unroll 8
        for (int cc = 0; cc < 256; ++cc)
            acc += w_s[cc * 33 + cr] * x_s[pl * 256 + cc];
    }

    float s = acc;
    if (z == 0) {
        const float sc = bn_g[cr] * rsqrtf(bn_v[cr] + 1e-5f);
        s = s * sc + (bn_b[cr] - bn_m[cr] * sc);
    }
    s = fmaxf(s, 0.f);
    g_yz[(((size_t)z * BB + b) * CR + cr) * 160 + p0 + pl] = s;
}

// ---------------- kernel B2: sigmoid gates ----------------
__global__ void s_kernel(const float* __restrict__ w_fh1, const float* __restrict__ w_fw1,
                         const float* __restrict__ w_fh2, const float* __restrict__ w_fw2) {
    const int a  = blockIdx.x;
    const int b  = blockIdx.y;
    const int oc = blockIdx.z;
    const float* wp = (a == 0) ? w_fh1 : (a == 1) ? w_fw1 : (a == 2) ? w_fh2 : w_fw2;
    const int z = a >> 1;
    const int off = (a & 1) * 80;

    __shared__ float ys[CR][80];
    __shared__ float wch[64][33];

    const int tid = threadIdx.x;
    for (int i = tid; i < CR * 80; i += 256) {
        const int cr = i / 80, p = i % 80;
        ys[cr][p] = g_yz[(((size_t)z * BB + b) * CR + cr) * 160 + off + p];
    }
    for (int i = tid; i < 64 * 32; i += 256) {
        const int ol = i >> 5, cr = i & 31;
        wch[ol][cr] = wp[(oc * 64 + ol) * CR + cr];
    }
    __syncthreads();

    const int ol = tid >> 2;
    const int hg = (tid & 3) * 20;
    float* dst = g_s + (((size_t)a * BB + b) * CHN + oc * 64 + ol) * 80;
    #pragma unroll
    for (int j = 0; j < 20; ++j) {
        const int h = hg + j;
        float s = 0.f;
        #pragma unroll
        for (int cr = 0; cr < CR; ++cr) s += wch[ol][cr] * ys[cr][h];
        dst[h] = 1.f / (1.f + __expf(-s));
    }
}

// ---------------- kernel C: tf32 mma.sync GEMM, 4 warps 64x64, reg double-buffer ----------------
#define BM 128
#define BN 128
#define BK 32
#define A_STAGE_FLOATS 4096               // 128x32 fragment-order
#define XS_STRIDE 136
#define X_STAGE_FLOATS (BK * XS_STRIDE)   // 4352
#define STAGE_FLOATS (A_STAGE_FLOATS + X_STAGE_FLOATS)  // 8448
#define NSTAGE 3
#define GEMM_SMEM (NSTAGE * STAGE_FLOATS * 4)           // 101376 bytes
#define NKT 32

struct Frag {
    uint4 a[4];
    unsigned b[8][2];
};

__global__ __launch_bounds__(128, 2)
void gemm_kernel(const float* __restrict__ rgb, const float* __restrict__ t,
                 float* __restrict__ out) {
    extern __shared__ float dynsmem[];

    const int b  = blockIdx.z;
    const int o_blk = blockIdx.y;
    const int o0 = o_blk * BM;
    const int p0 = blockIdx.x * BN;
    const int tid  = threadIdx.x;
    const int lane = tid & 31;
    const int warp = tid >> 5;     // 0..3
    const int wm = warp >> 1;      // 0..1  (64 rows)
    const int wn = warp & 1;       // 0..1  (64 cols)

    const float* rgbB = rgb + (size_t)b * CHN * HW;
    const float* tB   = t   + (size_t)b * CHN * HW;
    const float* wbase = g_wr + (size_t)o_blk * 32 * A_STAGE_FLOATS;

    float acc[4][8][4];
    #pragma unroll
    for (int i = 0; i < 4; ++i)
        #pragma unroll
        for (int j = 0; j < 8; ++j)
            #pragma unroll
            for (int e = 0; e < 4; ++e) acc[i][j][e] = 0.f;

    auto issue = [&](int stage, int kt) {
        const int k0 = kt * BK;
        const float* xb = (k0 < CHN) ? rgbB : tB;
        const int krow = k0 & (CHN - 1);
        float* As = dynsmem + stage * STAGE_FLOATS;
        float* Xs = As + A_STAGE_FLOATS;
        const float* asrc = wbase + (size_t)kt * A_STAGE_FLOATS;
        #pragma unroll
        for (int ps = 0; ps < 8; ++ps) {
            const int off = (tid + ps * 128) * 4;
            unsigned d = (unsigned)__cvta_generic_to_shared(&As[off]);
            CP_ASYNC16(d, asrc + off);
        }
        #pragma unroll
        for (int ps = 0; ps < 8; ++ps) {
            const int row = (tid >> 5) + ps * 4;
            const int cq  = (tid & 31) * 4;
            unsigned d = (unsigned)__cvta_generic_to_shared(&Xs[row * XS_STRIDE + cq]);
            CP_ASYNC16(d, xb + (size_t)(krow + row) * HW + p0 + cq);
        }
    };

    auto load_frag = [&](Frag& f, const float* As, int kk) {
        const uint4* a4 = reinterpret_cast<const uint4*>(As);
        const float* Xs = As + A_STAGE_FLOATS;
        #pragma unroll
        for (int mi = 0; mi < 4; ++mi)
            f.a[mi] = a4[((kk * 2 + wm) * 4 + mi) * 32 + lane];
        const int ka = kk * 8 + (lane & 3);
        const int cb = wn * 64 + (lane >> 2);
        #pragma unroll
        for (int ni = 0; ni < 8; ++ni) {
            const float* bp = &Xs[ka * XS_STRIDE + cb + ni * 8];
            f.b[ni][0] = f2tf32(bp[0]);
            f.b[ni][1] = f2tf32(bp[4 * XS_STRIDE]);
        }
    };

    auto mma_all = [&](const Frag& f) {
        #pragma unroll
        for (int mi = 0; mi < 4; ++mi)
            #pragma unroll
            for (int ni = 0; ni < 8; ++ni)
                mma_tf32(acc[mi][ni], f.a[mi].x, f.a[mi].y, f.a[mi].z, f.a[mi].w,
                         f.b[ni][0], f.b[ni][1]);
    };

    // prologue: stages 0 and 1 in flight; stage 0 visible after wait+sync
    issue(0, 0); CP_COMMIT();
    issue(1, 1); CP_COMMIT();
    CP_WAIT1();
    __syncthreads();

    Frag fr[2];
    load_frag(fr[0], dynsmem, 0);
    int cur = 0;

    for (int kt = 0; kt < NKT; ++kt) {
        if (kt + 2 < NKT) { issue((kt + 2) % NSTAGE, kt + 2); CP_COMMIT(); }

        const float* As = dynsmem + (kt % NSTAGE) * STAGE_FLOATS;

        #pragma unroll
        for (int kk = 0; kk < 3; ++kk) {
            load_frag(fr[cur ^ 1], As, kk + 1);
            mma_all(fr[cur]);
            cur ^= 1;
        }

        if (kt + 2 < NKT)      CP_WAIT1();
        else if (kt + 1 < NKT) CP_WAIT0();
        __syncthreads();

        mma_all(fr[cur]);
        if (kt + 1 < NKT)
            load_frag(fr[cur ^ 1], dynsmem + ((kt + 1) % NSTAGE) * STAGE_FLOATS, 0);
        cur ^= 1;
    }

    // Epilogue: gate and store
    const float* sh1 = g_s + (((size_t)0 * BB + b) * CHN) * 80;
    const float* sw1 = g_s + (((size_t)1 * BB + b) * CHN) * 80;
    const float* sh2 = g_s + (((size_t)2 * BB + b) * CHN) * 80;
    const float* sw2 = g_s + (((size_t)3 * BB + b) * CHN) * 80;
    float* outB = out + (size_t)b * CHN * HW;

    #pragma unroll
    for (int mi = 0; mi < 4; ++mi) {
        const int r = o0 + wm * 64 + mi * 16 + (lane >> 2);
        #pragma unroll
        for (int ni = 0; ni < 8; ++ni) {
            const int pc = p0 + wn * 64 + ni * 8 + 2 * (lane & 3);
            const int h = pc / 80;
            const int w = pc - h * 80;
            #pragma unroll
            for (int half = 0; half < 2; ++half) {
                const int o = r + half * 8;
                const float sh1v = sh1[o * 80 + h];
                const float sh2v = sh2[o * 80 + h];
                const float g0 = sh1v * sw1[o * 80 + w]     + sh2v * sw2[o * 80 + w];
                const float g1 = sh1v * sw1[o * 80 + w + 1] + sh2v * sw2[o * 80 + w + 1];
                float2 v;
                v.x = acc[mi][ni][half * 2 + 0] * g0;
                v.y = acc[mi][ni][half * 2 + 1] * g1;
                *reinterpret_cast<float2*>(outB + (size_t)o * HW + pc) = v;
            }
        }
    }
}

// ---------------- launch ----------------
extern "C" void kernel_launch(void* const* d_in, const int* in_sizes, int n_in,
                              void* d_out, int out_size) {
    const float* rgb    = (const float*)d_in[0];
    const float* t      = (const float*)d_in[1];
    const float* w_fuse = (const float*)d_in[2];
    const float* w_r1   = (const float*)d_in[3];
    const float* w_t1   = (const float*)d_in[4];
    const float* w_fh1  = (const float*)d_in[5];
    const float* w_fw1  = (const float*)d_in[6];
    const float* w_fh2  = (const float*)d_in[7];
    const float* w_fw2  = (const float*)d_in[8];
    const float* bn_g   = (const float*)d_in[9];
    const float* bn_b   = (const float*)d_in[10];
    const float* bn_m   = (const float*)d_in[11];
    const float* bn_v   = (const float*)d_in[12];
    float* out = (float*)d_out;

    cudaFuncSetAttribute(gemm_kernel, cudaFuncAttributeMaxDynamicSharedMemorySize, GEMM_SMEM);
    cudaFuncSetAttribute(mean_kernel, cudaFuncAttributeMaxDynamicSharedMemorySize, MEAN_SMEM);

    wrepack_kernel<<<128, 256>>>(w_fuse);
    mean_kernel<<<dim3(CHN / 4, BB, 2), 256, MEAN_SMEM>>>(rgb, t);
    yz_kernel<<<dim3(20, BB, 2), 256>>>(w_r1, w_t1, bn_g, bn_b, bn_m, bn_v);
    s_kernel<<<dim3(4, BB, 8), 256>>>(w_fh1, w_fw1, w_fh2, w_fw2);
    gemm_kernel<<<dim3(HW / BN, CHN / BM, BB), 128, GEMM_SMEM>>>(rgb, t, out);
}